// round 7
// baseline (speedup 1.0000x reference)
#include <cuda_runtime.h>
#include <math_constants.h>

#define BB 64
#define LL 4096
#define DD 512
#define NS 4                 // L-splits per batch row -> grid 256
#define CHUNK (LL / NS)      // 1024 rows per CTA
#define NPAIR (CHUNK / 2)    // 512 pairs (compile-time -> ptxas pipelines)
#define WARPS 8
#define NTHREADS (WARPS * 32)

// scratch: per (b, split): c[512] at local-max reference, then m, then s
__device__ float g_scratch[BB * NS * (DD + 2)];
__device__ int   g_done[BB];   // zero-init; combiner resets -> graph-replay safe

static __device__ __forceinline__ float ldcg(const float* p) {
    float v;
    asm volatile("ld.global.cg.f32 %0, [%1];" : "=f"(v) : "l"(p));
    return v;
}

__global__ void __launch_bounds__(NTHREADS, 2)
attn_fused(const float* __restrict__ h, const float* __restrict__ E,
           float* __restrict__ outp) {
    const int b     = blockIdx.x / NS;
    const int split = blockIdx.x % NS;
    const int tid   = threadIdx.x;
    const int wid   = tid >> 5;
    const int lane  = tid & 31;

    // load h[b] (512 floats): lane j holds float4 indices j + 32q
    const float4* h4 = (const float4*)(h + (size_t)b * DD);
    float4 hv[4];
#pragma unroll
    for (int q = 0; q < 4; q++) hv[q] = __ldg(h4 + lane + 32 * q);

    const float4* Eb  = (const float4*)(E + (size_t)b * LL * DD);
    const int row0    = split * CHUNK;

    float m = -CUDART_INF_F;
    float s = 0.f;
    float4 c[4];
#pragma unroll
    for (int q = 0; q < 4; q++) c[q] = make_float4(0.f, 0.f, 0.f, 0.f);

    // two rows per warp-iteration; static trip count lets ptxas pipeline
    for (int p = wid; p < NPAIR; p += WARPS) {
        const float4* rowA = Eb + (size_t)(row0 + 2 * p) * (DD / 4);
        const float4* rowB = rowA + (DD / 4);
        float4 vA[4], vB[4];
#pragma unroll
        for (int q = 0; q < 4; q++) vA[q] = __ldg(rowA + lane + 32 * q);
#pragma unroll
        for (int q = 0; q < 4; q++) vB[q] = __ldg(rowB + lane + 32 * q);

        float d0 = 0.f, d1 = 0.f;
#pragma unroll
        for (int q = 0; q < 4; q++) {
            d0 = fmaf(vA[q].x, hv[q].x, d0);
            d1 = fmaf(vB[q].x, hv[q].x, d1);
            d0 = fmaf(vA[q].y, hv[q].y, d0);
            d1 = fmaf(vB[q].y, hv[q].y, d1);
            d0 = fmaf(vA[q].z, hv[q].z, d0);
            d1 = fmaf(vB[q].z, hv[q].z, d1);
            d0 = fmaf(vA[q].w, hv[q].w, d0);
            d1 = fmaf(vB[q].w, hv[q].w, d1);
        }
        // interleaved warp reductions (two independent chains)
#pragma unroll
        for (int o = 16; o > 0; o >>= 1) {
            d0 += __shfl_xor_sync(0xffffffffu, d0, o);
            d1 += __shfl_xor_sync(0xffffffffu, d1, o);
        }
        const float e0 = d0, e1 = d1;
        const float emax = fmaxf(e0, e1);

        if (emax > m) {                    // warp-uniform, rarely taken
            const float sc = __expf(m - emax);
            s *= sc;
#pragma unroll
            for (int q = 0; q < 4; q++) {
                c[q].x *= sc; c[q].y *= sc; c[q].z *= sc; c[q].w *= sc;
            }
            m = emax;
        }
        const float p0 = __expf(e0 - m);
        const float p1 = __expf(e1 - m);
        s += p0 + p1;
#pragma unroll
        for (int q = 0; q < 4; q++) {
            c[q].x = fmaf(p0, vA[q].x, c[q].x);
            c[q].y = fmaf(p0, vA[q].y, c[q].y);
            c[q].z = fmaf(p0, vA[q].z, c[q].z);
            c[q].w = fmaf(p0, vA[q].w, c[q].w);
            c[q].x = fmaf(p1, vB[q].x, c[q].x);
            c[q].y = fmaf(p1, vB[q].y, c[q].y);
            c[q].z = fmaf(p1, vB[q].z, c[q].z);
            c[q].w = fmaf(p1, vB[q].w, c[q].w);
        }
    }

    // ---- combine the 8 warps within the CTA ----
    __shared__ float sm_c[WARPS][DD];
    __shared__ float sm_m[WARPS], sm_s[WARPS], sm_sc[WARPS];
    __shared__ float sm_mg, sm_stot;
    __shared__ int   sm_docmb;

#pragma unroll
    for (int q = 0; q < 4; q++) {
        const int d0i = 4 * lane + 128 * q;
        sm_c[wid][d0i + 0] = c[q].x;
        sm_c[wid][d0i + 1] = c[q].y;
        sm_c[wid][d0i + 2] = c[q].z;
        sm_c[wid][d0i + 3] = c[q].w;
    }
    if (lane == 0) { sm_m[wid] = m; sm_s[wid] = s; }
    __syncthreads();

    if (wid == 0) {
        float mw = (lane < WARPS) ? sm_m[lane] : -CUDART_INF_F;
        float mg = mw;
#pragma unroll
        for (int o = 16; o > 0; o >>= 1)
            mg = fmaxf(mg, __shfl_xor_sync(0xffffffffu, mg, o));
        float sc = (lane < WARPS) ? __expf(mw - mg) : 0.f;
        float st = (lane < WARPS) ? sm_s[lane] * sc : 0.f;
#pragma unroll
        for (int o = 16; o > 0; o >>= 1)
            st += __shfl_xor_sync(0xffffffffu, st, o);
        if (lane < WARPS) sm_sc[lane] = sc;
        if (lane == 0) { sm_mg = mg; sm_stot = st; }
    }
    __syncthreads();

    float* out = g_scratch + ((size_t)b * NS + split) * (DD + 2);
    for (int d = tid; d < DD; d += NTHREADS) {
        float acc = 0.f;
#pragma unroll
        for (int w = 0; w < WARPS; w++)
            acc = fmaf(sm_c[w][d], sm_sc[w], acc);
        out[d] = acc;
    }
    if (tid == 0) { out[DD] = sm_mg; out[DD + 1] = sm_stot; }

    // ---- last-CTA-per-batch combine (replaces pass2) ----
    __threadfence();
    if (tid == 0)
        sm_docmb = (atomicAdd(&g_done[b], 1) == NS - 1);
    __syncthreads();
    if (!sm_docmb) return;

    __shared__ float sm2_sc[NS];
    __shared__ float sm2_stot;
    const float* base = g_scratch + (size_t)b * NS * (DD + 2);

    if (tid == 0) {                       // NS=4: serial, fixed order
        float mg = -CUDART_INF_F;
#pragma unroll
        for (int i = 0; i < NS; i++)
            mg = fmaxf(mg, ldcg(base + (size_t)i * (DD + 2) + DD));
        float st = 0.f;
#pragma unroll
        for (int i = 0; i < NS; i++) {
            const float sc = __expf(ldcg(base + (size_t)i * (DD + 2) + DD) - mg);
            sm2_sc[i] = sc;
            st = fmaf(sc, ldcg(base + (size_t)i * (DD + 2) + DD + 1), st);
        }
        sm2_stot = st;
    }
    __syncthreads();

    const float inv = 1.f / (sm2_stot * (float)LL);
#pragma unroll
    for (int dd = 0; dd < DD / NTHREADS; dd++) {
        const int d = tid + dd * NTHREADS;
        float acc = 0.f;
#pragma unroll
        for (int i = 0; i < NS; i++)
            acc = fmaf(ldcg(base + (size_t)i * (DD + 2) + d), sm2_sc[i], acc);
        outp[(size_t)b * DD + d] = acc * inv;
    }

    if (tid == 0) g_done[b] = 0;          // reset for next graph replay
}

extern "C" void kernel_launch(void* const* d_in, const int* in_sizes, int n_in,
                              void* d_out, int out_size) {
    const float* h = (const float*)d_in[0];   // current_hidden [64, 512]
    const float* E = (const float*)d_in[1];   // encoder_outputs [64, 4096, 512]
    float* outp = (float*)d_out;              // [64, 512]

    attn_fused<<<BB * NS, NTHREADS>>>(h, E, outp);
}

// round 8
// speedup vs baseline: 1.0746x; 1.0746x over previous
#include <cuda_runtime.h>
#include <math_constants.h>

#define BB 64
#define LL 4096
#define DD 512
#define NS 4                 // L-splits per batch row -> grid 256
#define CHUNK (LL / NS)      // 1024 rows per CTA
#define NPAIR (CHUNK / 2)    // 512 pairs (compile-time -> ptxas pipelines)
#define WARPS 8
#define NTHREADS (WARPS * 32)

// scratch: per (b, split): c[512] at local-max reference, then m, then s
__device__ float g_scratch[BB * NS * (DD + 2)];
__device__ int   g_done[BB];   // zero-init; pass2 resets -> graph-replay safe

static __device__ __forceinline__ float ldcg(const float* p) {
    float v;
    asm volatile("ld.global.cg.f32 %0, [%1];" : "=f"(v) : "l"(p));
    return v;
}
static __device__ __forceinline__ int ld_acq(const int* p) {
    int v;
    asm volatile("ld.global.acquire.gpu.b32 %0, [%1];" : "=r"(v) : "l"(p));
    return v;
}

__global__ void __launch_bounds__(NTHREADS, 2)
attn_pass1(const float* __restrict__ h, const float* __restrict__ E) {
    const int b     = blockIdx.x / NS;
    const int split = blockIdx.x % NS;
    const int tid   = threadIdx.x;
    const int wid   = tid >> 5;
    const int lane  = tid & 31;

    // load h[b] (512 floats): lane j holds float4 indices j + 32q
    const float4* h4 = (const float4*)(h + (size_t)b * DD);
    float4 hv[4];
#pragma unroll
    for (int q = 0; q < 4; q++) hv[q] = __ldg(h4 + lane + 32 * q);

    const float4* Eb  = (const float4*)(E + (size_t)b * LL * DD);
    const int row0    = split * CHUNK;

    float m = -CUDART_INF_F;
    float s = 0.f;
    float4 c[4];
#pragma unroll
    for (int q = 0; q < 4; q++) c[q] = make_float4(0.f, 0.f, 0.f, 0.f);

    // two rows per warp-iteration; static trip count lets ptxas pipeline
    for (int p = wid; p < NPAIR; p += WARPS) {
        const float4* rowA = Eb + (size_t)(row0 + 2 * p) * (DD / 4);
        const float4* rowB = rowA + (DD / 4);
        float4 vA[4], vB[4];
#pragma unroll
        for (int q = 0; q < 4; q++) vA[q] = __ldg(rowA + lane + 32 * q);
#pragma unroll
        for (int q = 0; q < 4; q++) vB[q] = __ldg(rowB + lane + 32 * q);

        float d0 = 0.f, d1 = 0.f;
#pragma unroll
        for (int q = 0; q < 4; q++) {
            d0 = fmaf(vA[q].x, hv[q].x, d0);
            d1 = fmaf(vB[q].x, hv[q].x, d1);
            d0 = fmaf(vA[q].y, hv[q].y, d0);
            d1 = fmaf(vB[q].y, hv[q].y, d1);
            d0 = fmaf(vA[q].z, hv[q].z, d0);
            d1 = fmaf(vB[q].z, hv[q].z, d1);
            d0 = fmaf(vA[q].w, hv[q].w, d0);
            d1 = fmaf(vB[q].w, hv[q].w, d1);
        }
        // interleaved warp reductions (two independent chains)
#pragma unroll
        for (int o = 16; o > 0; o >>= 1) {
            d0 += __shfl_xor_sync(0xffffffffu, d0, o);
            d1 += __shfl_xor_sync(0xffffffffu, d1, o);
        }
        const float e0 = d0, e1 = d1;
        const float emax = fmaxf(e0, e1);

        if (emax > m) {                    // warp-uniform, rarely taken
            const float sc = __expf(m - emax);
            s *= sc;
#pragma unroll
            for (int q = 0; q < 4; q++) {
                c[q].x *= sc; c[q].y *= sc; c[q].z *= sc; c[q].w *= sc;
            }
            m = emax;
        }
        const float p0 = __expf(e0 - m);
        const float p1 = __expf(e1 - m);
        s += p0 + p1;
#pragma unroll
        for (int q = 0; q < 4; q++) {
            c[q].x = fmaf(p0, vA[q].x, c[q].x);
            c[q].y = fmaf(p0, vA[q].y, c[q].y);
            c[q].z = fmaf(p0, vA[q].z, c[q].z);
            c[q].w = fmaf(p0, vA[q].w, c[q].w);
            c[q].x = fmaf(p1, vB[q].x, c[q].x);
            c[q].y = fmaf(p1, vB[q].y, c[q].y);
            c[q].z = fmaf(p1, vB[q].z, c[q].z);
            c[q].w = fmaf(p1, vB[q].w, c[q].w);
        }
    }

    // PDL: allow pass2 to launch while we run the combine/flush epilogue
    asm volatile("griddepcontrol.launch_dependents;");

    // ---- combine the 8 warps within the CTA ----
    __shared__ float sm_c[WARPS][DD];
    __shared__ float sm_m[WARPS], sm_s[WARPS], sm_sc[WARPS];
    __shared__ float sm_mg, sm_stot;

#pragma unroll
    for (int q = 0; q < 4; q++) {
        const int d0i = 4 * lane + 128 * q;
        sm_c[wid][d0i + 0] = c[q].x;
        sm_c[wid][d0i + 1] = c[q].y;
        sm_c[wid][d0i + 2] = c[q].z;
        sm_c[wid][d0i + 3] = c[q].w;
    }
    if (lane == 0) { sm_m[wid] = m; sm_s[wid] = s; }
    __syncthreads();

    if (wid == 0) {
        float mw = (lane < WARPS) ? sm_m[lane] : -CUDART_INF_F;
        float mg = mw;
#pragma unroll
        for (int o = 16; o > 0; o >>= 1)
            mg = fmaxf(mg, __shfl_xor_sync(0xffffffffu, mg, o));
        float sc = (lane < WARPS) ? __expf(mw - mg) : 0.f;
        float st = (lane < WARPS) ? sm_s[lane] * sc : 0.f;
#pragma unroll
        for (int o = 16; o > 0; o >>= 1)
            st += __shfl_xor_sync(0xffffffffu, st, o);
        if (lane < WARPS) sm_sc[lane] = sc;
        if (lane == 0) { sm_mg = mg; sm_stot = st; }
    }
    __syncthreads();

    float* out = g_scratch + ((size_t)b * NS + split) * (DD + 2);
    for (int d = tid; d < DD; d += NTHREADS) {
        float acc = 0.f;
#pragma unroll
        for (int w = 0; w < WARPS; w++)
            acc = fmaf(sm_c[w][d], sm_sc[w], acc);
        out[d] = acc;
    }
    if (tid == 0) { out[DD] = sm_mg; out[DD + 1] = sm_stot; }

    // publish: fence then release-increment the per-batch flag
    __threadfence();
    __syncthreads();
    if (tid == 0) atomicAdd(&g_done[b], 1);
}

// 64 blocks x 256 threads: block b spins on its flag, then combines.
__global__ void __launch_bounds__(256)
attn_pass2(float* __restrict__ outp) {
    const int b   = blockIdx.x;
    const int tid = threadIdx.x;

    __shared__ float sm_sc[NS];
    __shared__ float sm_stot;

    // spin until all NS splits of b have flushed (PDL: we may start early)
    if (tid == 0) {
        while (ld_acq(&g_done[b]) != NS) __nanosleep(64);
    }
    __syncthreads();

    const float* base = g_scratch + (size_t)b * NS * (DD + 2);

    // parallel lane loads of the NS (m, s) pairs -> one L2 round
    if (tid < 32) {
        float mw = (tid < NS) ? ldcg(base + (size_t)tid * (DD + 2) + DD)
                              : -CUDART_INF_F;
        float sw = (tid < NS) ? ldcg(base + (size_t)tid * (DD + 2) + DD + 1)
                              : 0.f;
        float mg = mw;
#pragma unroll
        for (int o = 16; o > 0; o >>= 1)
            mg = fmaxf(mg, __shfl_xor_sync(0xffffffffu, mg, o));
        float sc = (tid < NS) ? __expf(mw - mg) : 0.f;
        float st = sw * sc;
#pragma unroll
        for (int o = 16; o > 0; o >>= 1)
            st += __shfl_xor_sync(0xffffffffu, st, o);
        if (tid < NS) sm_sc[tid] = sc;
        if (tid == 0) sm_stot = st;
    }
    __syncthreads();

    const float inv = 1.f / (sm_stot * (float)LL);
#pragma unroll
    for (int dd = 0; dd < 2; dd++) {
        const int d = tid + dd * 256;
        float acc = 0.f;
#pragma unroll
        for (int i = 0; i < NS; i++)
            acc = fmaf(ldcg(base + (size_t)i * (DD + 2) + d), sm_sc[i], acc);
        outp[(size_t)b * DD + d] = acc * inv;
    }

    if (tid == 0) g_done[b] = 0;          // reset for next graph replay
}

extern "C" void kernel_launch(void* const* d_in, const int* in_sizes, int n_in,
                              void* d_out, int out_size) {
    const float* h = (const float*)d_in[0];   // current_hidden [64, 512]
    const float* E = (const float*)d_in[1];   // encoder_outputs [64, 4096, 512]
    float* outp = (float*)d_out;              // [64, 512]

    attn_pass1<<<BB * NS, NTHREADS>>>(h, E);

    cudaLaunchConfig_t cfg = {};
    cfg.gridDim  = dim3(BB);
    cfg.blockDim = dim3(256);
    cudaLaunchAttribute attr[1];
    attr[0].id = cudaLaunchAttributeProgrammaticStreamSerialization;
    attr[0].val.programmaticStreamSerializationAllowed = 1;
    cfg.attrs = attr;
    cfg.numAttrs = 1;
    cudaLaunchKernelEx(&cfg, attn_pass2, outp);
}

// round 9
// speedup vs baseline: 1.0766x; 1.0019x over previous
#include <cuda_runtime.h>
#include <math_constants.h>

#define BB 64
#define LL 4096
#define DD 512
#define NS 4                 // L-splits per batch row -> 256 worker blocks
#define CHUNK (LL / NS)      // 1024 rows per CTA
#define NPAIR (CHUNK / 2)    // 512 pairs (compile-time -> ptxas pipelines)
#define WARPS 8
#define NTHREADS (WARPS * 32)
#define NWORK (BB * NS)      // 256
#define NGRID (NWORK + BB)   // + 64 combiner blocks

// scratch: per (b, split): c[512] at local-max reference, then m, then s
__device__ float g_scratch[BB * NS * (DD + 2)];
__device__ int   g_done[BB];   // zero-init; combiner resets -> graph-replay safe

static __device__ __forceinline__ float ldcg(const float* p) {
    float v;
    asm volatile("ld.global.cg.f32 %0, [%1];" : "=f"(v) : "l"(p));
    return v;
}
static __device__ __forceinline__ int ld_acq(const int* p) {
    int v;
    asm volatile("ld.global.acquire.gpu.b32 %0, [%1];" : "=r"(v) : "l"(p));
    return v;
}

__global__ void __launch_bounds__(NTHREADS, 2)
attn_one(const float* __restrict__ h, const float* __restrict__ E,
         float* __restrict__ outp) {
    const int tid  = threadIdx.x;
    const int wid  = tid >> 5;
    const int lane = tid & 31;

    // ================= combiner blocks =================
    if (blockIdx.x >= NWORK) {
        const int b = blockIdx.x - NWORK;

        __shared__ float sm2_sc[NS];
        __shared__ float sm2_stot;

        if (tid == 0) {
            while (ld_acq(&g_done[b]) != NS) __nanosleep(64);
        }
        __syncthreads();

        const float* base = g_scratch + (size_t)b * NS * (DD + 2);

        if (tid < 32) {      // parallel lane loads of the NS (m, s) pairs
            float mw = (tid < NS) ? ldcg(base + (size_t)tid * (DD + 2) + DD)
                                  : -CUDART_INF_F;
            float sw = (tid < NS) ? ldcg(base + (size_t)tid * (DD + 2) + DD + 1)
                                  : 0.f;
            float mg = mw;
#pragma unroll
            for (int o = 16; o > 0; o >>= 1)
                mg = fmaxf(mg, __shfl_xor_sync(0xffffffffu, mg, o));
            float sc = (tid < NS) ? __expf(mw - mg) : 0.f;
            float st = sw * sc;
#pragma unroll
            for (int o = 16; o > 0; o >>= 1)
                st += __shfl_xor_sync(0xffffffffu, st, o);
            if (tid < NS) sm2_sc[tid] = sc;
            if (tid == 0) sm2_stot = st;
        }
        __syncthreads();

        const float inv = 1.f / (sm2_stot * (float)LL);
#pragma unroll
        for (int dd = 0; dd < 2; dd++) {
            const int d = tid + dd * NTHREADS;
            float acc = 0.f;
#pragma unroll
            for (int i = 0; i < NS; i++)
                acc = fmaf(ldcg(base + (size_t)i * (DD + 2) + d), sm2_sc[i], acc);
            outp[(size_t)b * DD + d] = acc * inv;
        }
        if (tid == 0) g_done[b] = 0;      // reset for next graph replay
        return;
    }

    // ================= worker blocks (R6 pass1, unchanged) =================
    const int b     = blockIdx.x / NS;
    const int split = blockIdx.x % NS;

    // load h[b] (512 floats): lane j holds float4 indices j + 32q
    const float4* h4 = (const float4*)(h + (size_t)b * DD);
    float4 hv[4];
#pragma unroll
    for (int q = 0; q < 4; q++) hv[q] = __ldg(h4 + lane + 32 * q);

    const float4* Eb  = (const float4*)(E + (size_t)b * LL * DD);
    const int row0    = split * CHUNK;

    float m = -CUDART_INF_F;
    float s = 0.f;
    float4 c[4];
#pragma unroll
    for (int q = 0; q < 4; q++) c[q] = make_float4(0.f, 0.f, 0.f, 0.f);

    // two rows per warp-iteration; static trip count lets ptxas pipeline
    for (int p = wid; p < NPAIR; p += WARPS) {
        const float4* rowA = Eb + (size_t)(row0 + 2 * p) * (DD / 4);
        const float4* rowB = rowA + (DD / 4);
        float4 vA[4], vB[4];
#pragma unroll
        for (int q = 0; q < 4; q++) vA[q] = __ldg(rowA + lane + 32 * q);
#pragma unroll
        for (int q = 0; q < 4; q++) vB[q] = __ldg(rowB + lane + 32 * q);

        float d0 = 0.f, d1 = 0.f;
#pragma unroll
        for (int q = 0; q < 4; q++) {
            d0 = fmaf(vA[q].x, hv[q].x, d0);
            d1 = fmaf(vB[q].x, hv[q].x, d1);
            d0 = fmaf(vA[q].y, hv[q].y, d0);
            d1 = fmaf(vB[q].y, hv[q].y, d1);
            d0 = fmaf(vA[q].z, hv[q].z, d0);
            d1 = fmaf(vB[q].z, hv[q].z, d1);
            d0 = fmaf(vA[q].w, hv[q].w, d0);
            d1 = fmaf(vB[q].w, hv[q].w, d1);
        }
        // interleaved warp reductions (two independent chains)
#pragma unroll
        for (int o = 16; o > 0; o >>= 1) {
            d0 += __shfl_xor_sync(0xffffffffu, d0, o);
            d1 += __shfl_xor_sync(0xffffffffu, d1, o);
        }
        const float e0 = d0, e1 = d1;
        const float emax = fmaxf(e0, e1);

        if (emax > m) {                    // warp-uniform, rarely taken
            const float sc = __expf(m - emax);
            s *= sc;
#pragma unroll
            for (int q = 0; q < 4; q++) {
                c[q].x *= sc; c[q].y *= sc; c[q].z *= sc; c[q].w *= sc;
            }
            m = emax;
        }
        const float p0 = __expf(e0 - m);
        const float p1 = __expf(e1 - m);
        s += p0 + p1;
#pragma unroll
        for (int q = 0; q < 4; q++) {
            c[q].x = fmaf(p0, vA[q].x, c[q].x);
            c[q].y = fmaf(p0, vA[q].y, c[q].y);
            c[q].z = fmaf(p0, vA[q].z, c[q].z);
            c[q].w = fmaf(p0, vA[q].w, c[q].w);
            c[q].x = fmaf(p1, vB[q].x, c[q].x);
            c[q].y = fmaf(p1, vB[q].y, c[q].y);
            c[q].z = fmaf(p1, vB[q].z, c[q].z);
            c[q].w = fmaf(p1, vB[q].w, c[q].w);
        }
    }

    // ---- combine the 8 warps within the CTA ----
    __shared__ float sm_c[WARPS][DD];
    __shared__ float sm_m[WARPS], sm_s[WARPS], sm_sc[WARPS];
    __shared__ float sm_mg, sm_stot;

#pragma unroll
    for (int q = 0; q < 4; q++) {
        const int d0i = 4 * lane + 128 * q;
        sm_c[wid][d0i + 0] = c[q].x;
        sm_c[wid][d0i + 1] = c[q].y;
        sm_c[wid][d0i + 2] = c[q].z;
        sm_c[wid][d0i + 3] = c[q].w;
    }
    if (lane == 0) { sm_m[wid] = m; sm_s[wid] = s; }
    __syncthreads();

    if (wid == 0) {
        float mw = (lane < WARPS) ? sm_m[lane] : -CUDART_INF_F;
        float mg = mw;
#pragma unroll
        for (int o = 16; o > 0; o >>= 1)
            mg = fmaxf(mg, __shfl_xor_sync(0xffffffffu, mg, o));
        float sc = (lane < WARPS) ? __expf(mw - mg) : 0.f;
        float st = (lane < WARPS) ? sm_s[lane] * sc : 0.f;
#pragma unroll
        for (int o = 16; o > 0; o >>= 1)
            st += __shfl_xor_sync(0xffffffffu, st, o);
        if (lane < WARPS) sm_sc[lane] = sc;
        if (lane == 0) { sm_mg = mg; sm_stot = st; }
    }
    __syncthreads();

    float* out = g_scratch + ((size_t)b * NS + split) * (DD + 2);
    for (int d = tid; d < DD; d += NTHREADS) {
        float acc = 0.f;
#pragma unroll
        for (int w = 0; w < WARPS; w++)
            acc = fmaf(sm_c[w][d], sm_sc[w], acc);
        out[d] = acc;
    }
    if (tid == 0) { out[DD] = sm_mg; out[DD + 1] = sm_stot; }

    // publish: fence then increment the per-batch flag
    __threadfence();
    __syncthreads();
    if (tid == 0) atomicAdd(&g_done[b], 1);
}

extern "C" void kernel_launch(void* const* d_in, const int* in_sizes, int n_in,
                              void* d_out, int out_size) {
    const float* h = (const float*)d_in[0];   // current_hidden [64, 512]
    const float* E = (const float*)d_in[1];   // encoder_outputs [64, 4096, 512]
    float* outp = (float*)d_out;              // [64, 512]

    attn_one<<<NGRID, NTHREADS>>>(h, E, outp);
}

// round 10
// speedup vs baseline: 1.0778x; 1.0011x over previous
#include <cuda_runtime.h>
#include <math_constants.h>

#define BB 64
#define LL 4096
#define DD 512
#define NS 8                 // L-splits per batch row -> 512 worker blocks
#define CHUNK (LL / NS)      // 512 rows per CTA (compile-time)
#define WARPS 8
#define NTHREADS (WARPS * 32)
#define NWORK (BB * NS)      // 512
#define NGRID (NWORK + BB)   // + 64 combiner blocks = 576 (<= 592 slots @4/SM)

// scratch: per (b, split): c[512] at local-max reference, then m, then s
__device__ float g_scratch[BB * NS * (DD + 2)];
__device__ int   g_done[BB];   // zero-init; combiner resets -> graph-replay safe

static __device__ __forceinline__ float ldcg(const float* p) {
    float v;
    asm volatile("ld.global.cg.f32 %0, [%1];" : "=f"(v) : "l"(p));
    return v;
}
static __device__ __forceinline__ int ld_acq(const int* p) {
    int v;
    asm volatile("ld.global.acquire.gpu.b32 %0, [%1];" : "=r"(v) : "l"(p));
    return v;
}

__global__ void __launch_bounds__(NTHREADS, 4)
attn_one(const float* __restrict__ h, const float* __restrict__ E,
         float* __restrict__ outp) {
    const int tid  = threadIdx.x;
    const int wid  = tid >> 5;
    const int lane = tid & 31;

    // ================= combiner blocks =================
    if (blockIdx.x >= NWORK) {
        const int b = blockIdx.x - NWORK;

        __shared__ float sm2_sc[NS];
        __shared__ float sm2_stot;

        if (tid == 0) {
            while (ld_acq(&g_done[b]) != NS) __nanosleep(64);
        }
        __syncthreads();

        const float* base = g_scratch + (size_t)b * NS * (DD + 2);

        if (tid < 32) {      // parallel lane loads of the NS (m, s) pairs
            float mw = (tid < NS) ? ldcg(base + (size_t)tid * (DD + 2) + DD)
                                  : -CUDART_INF_F;
            float sw = (tid < NS) ? ldcg(base + (size_t)tid * (DD + 2) + DD + 1)
                                  : 0.f;
            float mg = mw;
#pragma unroll
            for (int o = 16; o > 0; o >>= 1)
                mg = fmaxf(mg, __shfl_xor_sync(0xffffffffu, mg, o));
            float sc = (tid < NS) ? __expf(mw - mg) : 0.f;
            float st = sw * sc;
#pragma unroll
            for (int o = 16; o > 0; o >>= 1)
                st += __shfl_xor_sync(0xffffffffu, st, o);
            if (tid < NS) sm2_sc[tid] = sc;
            if (tid == 0) sm2_stot = st;
        }
        __syncthreads();

        const float inv = 1.f / (sm2_stot * (float)LL);
#pragma unroll
        for (int dd = 0; dd < 2; dd++) {
            const int d = tid + dd * NTHREADS;
            float acc = 0.f;
#pragma unroll
            for (int i = 0; i < NS; i++)
                acc = fmaf(ldcg(base + (size_t)i * (DD + 2) + d), sm2_sc[i], acc);
            outp[(size_t)b * DD + d] = acc * inv;
        }
        if (tid == 0) g_done[b] = 0;      // reset for next graph replay
        return;
    }

    // ================= worker blocks (register-lean, 4 CTAs/SM) =============
    const int b     = blockIdx.x / NS;
    const int split = blockIdx.x % NS;

    const float4* h4  = (const float4*)(h + (size_t)b * DD);
    const float4* Eb  = (const float4*)(E + (size_t)b * LL * DD);
    const int row0    = split * CHUNK;

    float m = -CUDART_INF_F;
    float s = 0.f;
    float4 c[4];
#pragma unroll
    for (int q = 0; q < 4; q++) c[q] = make_float4(0.f, 0.f, 0.f, 0.f);

    // one row per warp-iteration; h streamed from L1 (stays resident there)
    for (int r = wid; r < CHUNK; r += WARPS) {
        const float4* row = Eb + (size_t)(row0 + r) * (DD / 4);
        float4 v[4];
#pragma unroll
        for (int q = 0; q < 4; q++) v[q] = __ldg(row + lane + 32 * q);

        float d0 = 0.f, d1 = 0.f;              // two chains halve FMA latency
#pragma unroll
        for (int q = 0; q < 4; q++) {
            const float4 hq = __ldg(h4 + lane + 32 * q);   // L1 hit
            d0 = fmaf(v[q].x, hq.x, d0);
            d1 = fmaf(v[q].y, hq.y, d1);
            d0 = fmaf(v[q].z, hq.z, d0);
            d1 = fmaf(v[q].w, hq.w, d1);
        }
        float e = d0 + d1;
#pragma unroll
        for (int o = 16; o > 0; o >>= 1)
            e += __shfl_xor_sync(0xffffffffu, e, o);

        if (e > m) {                           // warp-uniform, rarely taken
            const float sc = __expf(m - e);
            s *= sc;
#pragma unroll
            for (int q = 0; q < 4; q++) {
                c[q].x *= sc; c[q].y *= sc; c[q].z *= sc; c[q].w *= sc;
            }
            m = e;
        }
        const float p = __expf(e - m);
        s += p;
#pragma unroll
        for (int q = 0; q < 4; q++) {
            c[q].x = fmaf(p, v[q].x, c[q].x);
            c[q].y = fmaf(p, v[q].y, c[q].y);
            c[q].z = fmaf(p, v[q].z, c[q].z);
            c[q].w = fmaf(p, v[q].w, c[q].w);
        }
    }

    // ---- combine the 8 warps within the CTA ----
    __shared__ float sm_c[WARPS][DD];
    __shared__ float sm_m[WARPS], sm_s[WARPS], sm_sc[WARPS];
    __shared__ float sm_mg, sm_stot;

#pragma unroll
    for (int q = 0; q < 4; q++) {
        const int d0i = 4 * lane + 128 * q;
        sm_c[wid][d0i + 0] = c[q].x;
        sm_c[wid][d0i + 1] = c[q].y;
        sm_c[wid][d0i + 2] = c[q].z;
        sm_c[wid][d0i + 3] = c[q].w;
    }
    if (lane == 0) { sm_m[wid] = m; sm_s[wid] = s; }
    __syncthreads();

    if (wid == 0) {
        float mw = (lane < WARPS) ? sm_m[lane] : -CUDART_INF_F;
        float mg = mw;
#pragma unroll
        for (int o = 16; o > 0; o >>= 1)
            mg = fmaxf(mg, __shfl_xor_sync(0xffffffffu, mg, o));
        float sc = (lane < WARPS) ? __expf(mw - mg) : 0.f;
        float st = (lane < WARPS) ? sm_s[lane] * sc : 0.f;
#pragma unroll
        for (int o = 16; o > 0; o >>= 1)
            st += __shfl_xor_sync(0xffffffffu, st, o);
        if (lane < WARPS) sm_sc[lane] = sc;
        if (lane == 0) { sm_mg = mg; sm_stot = st; }
    }
    __syncthreads();

    float* out = g_scratch + ((size_t)b * NS + split) * (DD + 2);
    for (int d = tid; d < DD; d += NTHREADS) {
        float acc = 0.f;
#pragma unroll
        for (int w = 0; w < WARPS; w++)
            acc = fmaf(sm_c[w][d], sm_sc[w], acc);
        out[d] = acc;
    }
    if (tid == 0) { out[DD] = sm_mg; out[DD + 1] = sm_stot; }

    // publish: fence then increment the per-batch flag
    __threadfence();
    __syncthreads();
    if (tid == 0) atomicAdd(&g_done[b], 1);
}

extern "C" void kernel_launch(void* const* d_in, const int* in_sizes, int n_in,
                              void* d_out, int out_size) {
    const float* h = (const float*)d_in[0];   // current_hidden [64, 512]
    const float* E = (const float*)d_in[1];   // encoder_outputs [64, 4096, 512]
    float* outp = (float*)d_out;              // [64, 512]

    attn_one<<<NGRID, NTHREADS>>>(h, E, outp);
}

// round 11
// speedup vs baseline: 1.0944x; 1.0155x over previous
#include <cuda_runtime.h>
#include <math_constants.h>

#define BB 64
#define LL 4096
#define DD 512
#define NS 8                 // L-splits per batch row -> 512 worker blocks
#define CHUNK (LL / NS)      // 512 rows per CTA (compile-time)
#define WARPS 8
#define NTHREADS (WARPS * 32)
#define NWORK (BB * NS)      // 512
#define NGRID (NWORK + BB)   // 64 combiner blocks (first) + 512 workers = 576
#define SSTR (DD + 4)        // scratch row stride: 516 floats, 16B-aligned

// scratch: per (b, split): c[512] at local-max reference, m at [DD], s at [DD+1]
__device__ __align__(16) float g_scratch[BB * NS * SSTR];
__device__ int g_done[BB];   // zero-init; combiner resets -> graph-replay safe

static __device__ __forceinline__ float4 ldcg4(const float4* p) {
    float4 v;
    asm volatile("ld.global.cg.v4.f32 {%0,%1,%2,%3}, [%4];"
                 : "=f"(v.x), "=f"(v.y), "=f"(v.z), "=f"(v.w) : "l"(p));
    return v;
}
static __device__ __forceinline__ float ldcg(const float* p) {
    float v;
    asm volatile("ld.global.cg.f32 %0, [%1];" : "=f"(v) : "l"(p));
    return v;
}
static __device__ __forceinline__ int ld_acq(const int* p) {
    int v;
    asm volatile("ld.global.acquire.gpu.b32 %0, [%1];" : "=r"(v) : "l"(p));
    return v;
}
static __device__ __forceinline__ void red_release_add(int* p, int v) {
    asm volatile("red.release.gpu.global.add.s32 [%0], %1;" :: "l"(p), "r"(v)
                 : "memory");
}

__global__ void __launch_bounds__(NTHREADS, 4)
attn_one(const float* __restrict__ h, const float* __restrict__ E,
         float* __restrict__ outp) {
    const int tid  = threadIdx.x;
    const int wid  = tid >> 5;
    const int lane = tid & 31;

    // ================= combiner blocks (0..BB-1): resident from wave 1 ======
    if (blockIdx.x < BB) {
        const int b = blockIdx.x;

        __shared__ float sm2_sc[NS];
        __shared__ float sm2_stot;

        if (tid == 0) {
            while (ld_acq(&g_done[b]) != NS) __nanosleep(32);
        }
        __syncthreads();

        const float* base = g_scratch + (size_t)b * NS * SSTR;

        if (tid < 32) {      // parallel lane loads of the NS (m, s) pairs
            float mw = (tid < NS) ? ldcg(base + (size_t)tid * SSTR + DD)
                                  : -CUDART_INF_F;
            float sw = (tid < NS) ? ldcg(base + (size_t)tid * SSTR + DD + 1)
                                  : 0.f;
            float mg = mw;
#pragma unroll
            for (int o = 16; o > 0; o >>= 1)
                mg = fmaxf(mg, __shfl_xor_sync(0xffffffffu, mg, o));
            float sc = (tid < NS) ? __expf(mw - mg) : 0.f;
            float st = sw * sc;
#pragma unroll
            for (int o = 16; o > 0; o >>= 1)
                st += __shfl_xor_sync(0xffffffffu, st, o);
            if (tid < NS) sm2_sc[tid] = sc;
            if (tid == 0) sm2_stot = st;
        }
        __syncthreads();

        if (tid < DD / 4) {                    // 128 threads, float4 lanes
            const float inv = 1.f / (sm2_stot * (float)LL);
            float4 acc = make_float4(0.f, 0.f, 0.f, 0.f);
#pragma unroll
            for (int i = 0; i < NS; i++) {
                const float4 v =
                    ldcg4((const float4*)(base + (size_t)i * SSTR) + tid);
                const float sc = sm2_sc[i];
                acc.x = fmaf(v.x, sc, acc.x);
                acc.y = fmaf(v.y, sc, acc.y);
                acc.z = fmaf(v.z, sc, acc.z);
                acc.w = fmaf(v.w, sc, acc.w);
            }
            acc.x *= inv; acc.y *= inv; acc.z *= inv; acc.w *= inv;
            ((float4*)(outp + (size_t)b * DD))[tid] = acc;
        }
        if (tid == 0) g_done[b] = 0;      // reset for next graph replay
        return;
    }

    // ================= worker blocks (R10 mainloop, unchanged) ==============
    const int wk    = blockIdx.x - BB;
    const int b     = wk / NS;
    const int split = wk % NS;

    const float4* h4  = (const float4*)(h + (size_t)b * DD);
    const float4* Eb  = (const float4*)(E + (size_t)b * LL * DD);
    const int row0    = split * CHUNK;

    float m = -CUDART_INF_F;
    float s = 0.f;
    float4 c[4];
#pragma unroll
    for (int q = 0; q < 4; q++) c[q] = make_float4(0.f, 0.f, 0.f, 0.f);

    // one row per warp-iteration; h streamed from L1 (stays resident there)
    for (int r = wid; r < CHUNK; r += WARPS) {
        const float4* row = Eb + (size_t)(row0 + r) * (DD / 4);
        float4 v[4];
#pragma unroll
        for (int q = 0; q < 4; q++) v[q] = __ldg(row + lane + 32 * q);

        float d0 = 0.f, d1 = 0.f;              // two chains halve FMA latency
#pragma unroll
        for (int q = 0; q < 4; q++) {
            const float4 hq = __ldg(h4 + lane + 32 * q);   // L1 hit
            d0 = fmaf(v[q].x, hq.x, d0);
            d1 = fmaf(v[q].y, hq.y, d1);
            d0 = fmaf(v[q].z, hq.z, d0);
            d1 = fmaf(v[q].w, hq.w, d1);
        }
        float e = d0 + d1;
#pragma unroll
        for (int o = 16; o > 0; o >>= 1)
            e += __shfl_xor_sync(0xffffffffu, e, o);

        if (e > m) {                           // warp-uniform, rarely taken
            const float sc = __expf(m - e);
            s *= sc;
#pragma unroll
            for (int q = 0; q < 4; q++) {
                c[q].x *= sc; c[q].y *= sc; c[q].z *= sc; c[q].w *= sc;
            }
            m = e;
        }
        const float p = __expf(e - m);
        s += p;
#pragma unroll
        for (int q = 0; q < 4; q++) {
            c[q].x = fmaf(p, v[q].x, c[q].x);
            c[q].y = fmaf(p, v[q].y, c[q].y);
            c[q].z = fmaf(p, v[q].z, c[q].z);
            c[q].w = fmaf(p, v[q].w, c[q].w);
        }
    }

    // ---- combine the 8 warps within the CTA ----
    __shared__ __align__(16) float sm_c[WARPS][DD];
    __shared__ float sm_m[WARPS], sm_s[WARPS], sm_sc[WARPS];
    __shared__ float sm_mg, sm_stot;

#pragma unroll
    for (int q = 0; q < 4; q++) {
        const int d0i = 4 * lane + 128 * q;
        sm_c[wid][d0i + 0] = c[q].x;
        sm_c[wid][d0i + 1] = c[q].y;
        sm_c[wid][d0i + 2] = c[q].z;
        sm_c[wid][d0i + 3] = c[q].w;
    }
    if (lane == 0) { sm_m[wid] = m; sm_s[wid] = s; }
    __syncthreads();

    if (wid == 0) {
        float mw = (lane < WARPS) ? sm_m[lane] : -CUDART_INF_F;
        float mg = mw;
#pragma unroll
        for (int o = 16; o > 0; o >>= 1)
            mg = fmaxf(mg, __shfl_xor_sync(0xffffffffu, mg, o));
        float sc = (lane < WARPS) ? __expf(mw - mg) : 0.f;
        float st = (lane < WARPS) ? sm_s[lane] * sc : 0.f;
#pragma unroll
        for (int o = 16; o > 0; o >>= 1)
            st += __shfl_xor_sync(0xffffffffu, st, o);
        if (lane < WARPS) sm_sc[lane] = sc;
        if (lane == 0) { sm_mg = mg; sm_stot = st; }
    }
    __syncthreads();

    // vectorized flush: 128 threads x float4
    float* out = g_scratch + ((size_t)b * NS + split) * SSTR;
    if (tid < DD / 4) {
        float4 acc = make_float4(0.f, 0.f, 0.f, 0.f);
#pragma unroll
        for (int w = 0; w < WARPS; w++) {
            const float4 v = ((const float4*)sm_c[w])[tid];
            const float sc = sm_sc[w];
            acc.x = fmaf(v.x, sc, acc.x);
            acc.y = fmaf(v.y, sc, acc.y);
            acc.z = fmaf(v.z, sc, acc.z);
            acc.w = fmaf(v.w, sc, acc.w);
        }
        ((float4*)out)[tid] = acc;
    }
    if (tid == 0) { out[DD] = sm_mg; out[DD + 1] = sm_stot; }

    // publish: release-ordered increment (orders prior writes, no full membar)
    __syncthreads();
    if (tid == 0) red_release_add(&g_done[b], 1);
}

extern "C" void kernel_launch(void* const* d_in, const int* in_sizes, int n_in,
                              void* d_out, int out_size) {
    const float* h = (const float*)d_in[0];   // current_hidden [64, 512]
    const float* E = (const float*)d_in[1];   // encoder_outputs [64, 4096, 512]
    float* outp = (float*)d_out;              // [64, 512]

    attn_one<<<NGRID, NTHREADS>>>(h, E, outp);
}